// round 3
// baseline (speedup 1.0000x reference)
#include <cuda_runtime.h>
#include <cuda_fp16.h>
#include <cstdint>

// ============================================================================
// shift_Windows == 4 batched GEMMs:  Out[o,p] = sum_k W[o,k] * X[k,p] + bias[o]
//   per (b in {0,1}, g in {0,1}):  M(o)=1024, N(p)=13824, K=1024
//   X[k=s'*32+c', p] = x[b, c', t', p],  t' = (g*32 + s' - 16) & 63
//   Out row o=s*32+c  -> out[b, c, t, p], t = (g*32 + s - 16) & 63  (same map)
//
// Toolchain compiles for baseline compute_103 (no 'a' features) -> tcgen05 is
// unavailable. Use classic mma.sync.m16n8k16 (HMMA) + cp.async + ldmatrix.
// Both operands prepass-converted to fp16 in __device__ scratch so every
// global load is a contiguous 16B cp.async.
// ============================================================================

#define HP3        13824     // 24^3 spatial positions per (b, t)
#define CH_STRIDE  884736    // 64*13824  (channel stride in x/out, elements)
#define B_STRIDE   28311552  // 32*884736 (batch stride, elements)

#define M_TILE 128           // o rows per CTA
#define N_TILE 128           // p cols per CTA
#define K_CHUNK 64
#define N_CHUNKS 16          // 1024 / 64

#define OFF_A 0              // A = W tile: [128 o][64 k] fp16, 128B rows, x2 bufs
#define OFF_B 32768          // B = X tile: [64 k][128 p] fp16, 256B rows, x2 bufs
#define SMEM_BYTES 65536

__device__ __half d_Wh[1024 * 1024];      // fp16 W
__device__ __half d_Xh[56623104];         // fp16 x  (2*32*96^3)

// ---------------- helpers ----------------
__device__ __forceinline__ uint32_t smem_to_u32(const void* p) {
    uint32_t a;
    asm("{ .reg .u64 t; cvta.to.shared.u64 t, %1; cvt.u32.u64 %0, t; }"
        : "=r"(a) : "l"(p));
    return a;
}
#define CP_ASYNC16(dst, src) \
    asm volatile("cp.async.cg.shared.global [%0], [%1], 16;" :: "r"(dst), "l"(src))
#define CP_COMMIT() asm volatile("cp.async.commit_group;" ::: "memory")
#define CP_WAIT(n)  asm volatile("cp.async.wait_group %0;" :: "n"(n) : "memory")

#define LDMATRIX_X4(r0, r1, r2, r3, addr) \
    asm volatile("ldmatrix.sync.aligned.m8n8.x4.shared.b16 {%0,%1,%2,%3}, [%4];" \
                 : "=r"(r0), "=r"(r1), "=r"(r2), "=r"(r3) : "r"(addr))
#define LDMATRIX_X4_T(r0, r1, r2, r3, addr) \
    asm volatile("ldmatrix.sync.aligned.m8n8.x4.trans.shared.b16 {%0,%1,%2,%3}, [%4];" \
                 : "=r"(r0), "=r"(r1), "=r"(r2), "=r"(r3) : "r"(addr))

#define MMA16816(d, a0, a1, a2, a3, b0, b1) \
    asm volatile("mma.sync.aligned.m16n8k16.row.col.f32.f16.f16.f32 " \
                 "{%0,%1,%2,%3}, {%4,%5,%6,%7}, {%8,%9}, {%0,%1,%2,%3};" \
                 : "+f"((d)[0]), "+f"((d)[1]), "+f"((d)[2]), "+f"((d)[3]) \
                 : "r"(a0), "r"(a1), "r"(a2), "r"(a3), "r"(b0), "r"(b1))

// ---------------- prepasses: fp32 -> fp16 ----------------
__global__ void __launch_bounds__(256) wconv_kernel(const float* __restrict__ W) {
    int i = blockIdx.x * 256 + threadIdx.x;        // 262144 float4's
    float4 v = ((const float4*)W)[i];
    __half2 a = __float22half2_rn(make_float2(v.x, v.y));
    __half2 c = __float22half2_rn(make_float2(v.z, v.w));
    uint2 u;
    u.x = *reinterpret_cast<const uint32_t*>(&a);
    u.y = *reinterpret_cast<const uint32_t*>(&c);
    ((uint2*)d_Wh)[i] = u;
}
__global__ void __launch_bounds__(256) xconv_kernel(const float* __restrict__ x) {
    int i = blockIdx.x * 256 + threadIdx.x;        // 14155776 float4's
    float4 v = ((const float4*)x)[i];
    __half2 a = __float22half2_rn(make_float2(v.x, v.y));
    __half2 c = __float22half2_rn(make_float2(v.z, v.w));
    uint2 u;
    u.x = *reinterpret_cast<const uint32_t*>(&a);
    u.y = *reinterpret_cast<const uint32_t*>(&c);
    ((uint2*)d_Xh)[i] = u;
}

// ---------------- main GEMM ----------------
__global__ void __launch_bounds__(256, 2)
swin_gemm_kernel(const float* __restrict__ bias, float* __restrict__ out) {
    extern __shared__ char sm[];
    const uint32_t smb = smem_to_u32(sm);
    const int tid  = threadIdx.x;
    const int lane = tid & 31;
    const int warp = tid >> 5;          // 0..7
    const int warp_m = warp & 3;        // o sub-tile (32 rows)
    const int warp_n = warp >> 2;       // p sub-tile (64 cols)

    const int o_base = blockIdx.x * M_TILE;
    const int p_base = blockIdx.y * N_TILE;
    const int bg = blockIdx.z;
    const int b  = bg >> 1;
    const int g  = bg & 1;

    float acc[2][8][4];
    #pragma unroll
    for (int mi = 0; mi < 2; mi++)
        #pragma unroll
        for (int ni = 0; ni < 8; ni++)
            #pragma unroll
            for (int r = 0; r < 4; r++) acc[mi][ni][r] = 0.f;

    // ---- tile loaders (cp.async, both contiguous 16B) ----
    auto load_tiles = [&](int buf, int kc) {
        // A = W[o_base..+128][kc*64..+64], rows 128B, SW128-style swizzle
        #pragma unroll
        for (int i = 0; i < 4; i++) {
            int cid = tid + i * 256;            // 1024 x 16B chunks
            int o = cid >> 3, c16 = cid & 7;
            const __half* src = d_Wh + (size_t)(o_base + o) * 1024 + kc * 64 + c16 * 8;
            uint32_t dst = smb + OFF_A + buf * 16384 + o * 128
                         + ((c16 * 16) ^ ((o & 7) << 4));
            CP_ASYNC16(dst, src);
        }
        // B = X[kc*64..+64][p_base..+128], rows 256B, swizzle by (k&7)
        #pragma unroll
        for (int i = 0; i < 4; i++) {
            int cid = tid + i * 256;            // 1024 x 16B chunks
            int kk = cid >> 4, c16 = cid & 15;
            int kg = kc * 64 + kk;
            int sp = kg >> 5, cp = kg & 31;
            int tp = ((g << 5) + sp - 16) & 63;
            const __half* src = d_Xh + (size_t)b * B_STRIDE + (size_t)cp * CH_STRIDE
                              + tp * HP3 + p_base + c16 * 8;
            uint32_t dst = smb + OFF_B + buf * 16384 + kk * 256
                         + ((c16 * 16) ^ ((kk & 7) << 4));
            CP_ASYNC16(dst, src);
        }
    };

    load_tiles(0, 0);
    CP_COMMIT();

    #pragma unroll 1
    for (int kc = 0; kc < N_CHUNKS; kc++) {
        const int buf = kc & 1;
        if (kc + 1 < N_CHUNKS) {
            load_tiles(buf ^ 1, kc + 1);
            CP_COMMIT();
            CP_WAIT(1);
        } else {
            CP_WAIT(0);
        }
        __syncthreads();

        const uint32_t abase = smb + OFF_A + buf * 16384;
        const uint32_t bbase = smb + OFF_B + buf * 16384;
        #pragma unroll
        for (int k16 = 0; k16 < 4; k16++) {
            uint32_t a[2][4], bb[4][4];
            #pragma unroll
            for (int mi = 0; mi < 2; mi++) {
                int row = warp_m * 32 + mi * 16 + (lane & 15);
                int col = k16 * 32 + (lane >> 4) * 16;
                uint32_t addr = abase + row * 128 + (col ^ ((row & 7) << 4));
                LDMATRIX_X4(a[mi][0], a[mi][1], a[mi][2], a[mi][3], addr);
            }
            #pragma unroll
            for (int ni = 0; ni < 4; ni++) {
                int row = k16 * 16 + (lane & 15);
                int col = warp_n * 128 + ni * 32 + (lane >> 4) * 16;
                uint32_t addr = bbase + row * 256 + (col ^ ((row & 7) << 4));
                LDMATRIX_X4_T(bb[ni][0], bb[ni][1], bb[ni][2], bb[ni][3], addr);
            }
            #pragma unroll
            for (int mi = 0; mi < 2; mi++)
                #pragma unroll
                for (int ni = 0; ni < 4; ni++) {
                    MMA16816(acc[mi][2 * ni],     a[mi][0], a[mi][1], a[mi][2], a[mi][3],
                             bb[ni][0], bb[ni][1]);
                    MMA16816(acc[mi][2 * ni + 1], a[mi][0], a[mi][1], a[mi][2], a[mi][3],
                             bb[ni][2], bb[ni][3]);
                }
        }
        __syncthreads();
    }

    // ---- epilogue: D[m=o, n=p] + bias[o] -> out[b, c, t, p_base + ...]
    #pragma unroll
    for (int mi = 0; mi < 2; mi++) {
        #pragma unroll
        for (int rr = 0; rr < 2; rr++) {
            int o = o_base + warp_m * 32 + mi * 16 + rr * 8 + (lane >> 2);
            int s = o >> 5, c = o & 31;
            int t = ((g << 5) + s - 16) & 63;
            float bv = __ldg(&bias[o]);
            float* orow = out + (size_t)b * B_STRIDE + (size_t)c * CH_STRIDE
                        + t * HP3 + p_base + warp_n * 64 + 2 * (lane & 3);
            #pragma unroll
            for (int ni = 0; ni < 8; ni++) {
                float2 v;
                v.x = acc[mi][ni][rr * 2 + 0] + bv;
                v.y = acc[mi][ni][rr * 2 + 1] + bv;
                *reinterpret_cast<float2*>(orow + ni * 8) = v;
            }
        }
    }
}

// ---------------- launch ----------------
extern "C" void kernel_launch(void* const* d_in, const int* in_sizes, int n_in,
                              void* d_out, int out_size) {
    const float* x    = (const float*)d_in[0];   // (2,32,96,96,96) fp32
    const float* W    = (const float*)d_in[1];   // (1024,1024) fp32
    const float* bias = (const float*)d_in[2];   // (1024,) fp32
    float* out = (float*)d_out;

    static bool attr_set = false;
    cudaFuncSetAttribute(swin_gemm_kernel,
                         cudaFuncAttributeMaxDynamicSharedMemorySize, SMEM_BYTES);
    (void)attr_set;

    wconv_kernel<<<1024, 256>>>(W);
    xconv_kernel<<<55296, 256>>>(x);

    dim3 grid(1024 / M_TILE, HP3 / N_TILE, 4);   // (8, 108, 4); x fastest -> X L2 reuse
    swin_gemm_kernel<<<grid, 256, SMEM_BYTES>>>(bias, out);
}